// round 10
// baseline (speedup 1.0000x reference)
#include <cuda_runtime.h>
#include <math.h>

#define Nn 8192
#define FEAT 128
#define C1 10
#define C2 5
#define JSPLIT 4
#define TJ 512
#define RPB 32   // rows per block in spmm (8 warps x 4 rows)
#define RW 4     // rows per warp

// ---------------- scratch (static device globals; no allocation) ----------------
__device__ float g_dinv[Nn];
__device__ float g_s1[Nn * C1];
__device__ float g_h1[Nn * C1];
__device__ float g_s2[Nn * C2];
__device__ float g_V1[JSPLIT][Nn * C1];
__device__ float g_V2[JSPLIT][Nn * C2];
__device__ float g_part2[Nn / 256][C2];

// ---------------- 1) degree / dinv ----------------
__global__ void deg_kernel(const float* __restrict__ adj) {
    __shared__ int sc[256];
    int i = blockIdx.x;
    const float4* row = reinterpret_cast<const float4*>(adj + (size_t)i * Nn);
    int cnt = 0;
    for (int k = threadIdx.x; k < Nn / 4; k += 256) {
        float4 v = row[k];
        cnt += (v.x > 0.f) + (v.y > 0.f) + (v.z > 0.f) + (v.w > 0.f);
    }
    sc[threadIdx.x] = cnt;
    __syncthreads();
    for (int s = 128; s > 0; s >>= 1) {
        if (threadIdx.x < s) sc[threadIdx.x] += sc[threadIdx.x + s];
        __syncthreads();
    }
    if (threadIdx.x == 0) g_dinv[i] = rsqrtf((float)sc[0]);
}

// ---------------- 2) s1 = (x @ W1) * dinv ----------------
__global__ void u1_kernel(const float* __restrict__ x, const float* __restrict__ W1) {
    __shared__ float w[FEAT * C1];
    for (int t = threadIdx.x; t < FEAT * C1; t += 256) w[t] = W1[t];
    __syncthreads();
    int warp = threadIdx.x >> 5, lane = threadIdx.x & 31;
    int i = blockIdx.x * 8 + warp;
    float4 xv = reinterpret_cast<const float4*>(x + (size_t)i * FEAT)[lane];
    float xs[4] = {xv.x, xv.y, xv.z, xv.w};
    float acc[C1];
#pragma unroll
    for (int c = 0; c < C1; c++) acc[c] = 0.f;
#pragma unroll
    for (int kk = 0; kk < 4; kk++) {
        int k = lane * 4 + kk;
#pragma unroll
        for (int c = 0; c < C1; c++) acc[c] = fmaf(xs[kk], w[k * C1 + c], acc[c]);
    }
#pragma unroll
    for (int c = 0; c < C1; c++) {
        float v = acc[c];
#pragma unroll
        for (int o = 16; o; o >>= 1) v += __shfl_xor_sync(0xffffffffu, v, o);
        if (lane == 0) g_s1[i * C1 + c] = v * g_dinv[i];
    }
}

// ---------------- 3/5) SpMM: Vpart[split] = adj[:, jrange] @ s[jrange, :] ----------------
template <int C, bool L1>
__global__ void __launch_bounds__(256) spmm_kernel(const float* __restrict__ adj) {
    const float* __restrict__ s = L1 ? g_s1 : g_s2;
    float* __restrict__ Vpart = L1 ? &g_V1[0][0] : &g_V2[0][0];

    __shared__ float ss[C][TJ];
    int warp = threadIdx.x >> 5, lane = threadIdx.x & 31;
    int i0 = blockIdx.x * RPB + warp * RW;
    int jbase = blockIdx.y * (Nn / JSPLIT);

    float acc[RW][C];
#pragma unroll
    for (int r = 0; r < RW; r++)
#pragma unroll
        for (int c = 0; c < C; c++) acc[r][c] = 0.f;

    for (int jc = 0; jc < Nn / JSPLIT; jc += TJ) {
        __syncthreads();
        // coalesced global read of the s-tile, transposed store to smem [C][TJ]
        for (int t = threadIdx.x; t < TJ * C; t += 256) {
            float v = s[(size_t)(jbase + jc) * C + t];
            int c = t % C, jj = t / C;
            ss[c][jj] = v;
        }
        __syncthreads();
#pragma unroll
        for (int it = 0; it < TJ; it += 128) {
            int jj = it + lane * 4;
            const float* arow = adj + (size_t)i0 * Nn + (jbase + jc + jj);
            float4 a[RW];
#pragma unroll
            for (int r = 0; r < RW; r++)
                a[r] = *reinterpret_cast<const float4*>(arow + (size_t)r * Nn);
#pragma unroll
            for (int c = 0; c < C; c++) {
                float4 sv = *reinterpret_cast<const float4*>(&ss[c][jj]);
#pragma unroll
                for (int r = 0; r < RW; r++) {
                    acc[r][c] = fmaf(a[r].x, sv.x, acc[r][c]);
                    acc[r][c] = fmaf(a[r].y, sv.y, acc[r][c]);
                    acc[r][c] = fmaf(a[r].z, sv.z, acc[r][c]);
                    acc[r][c] = fmaf(a[r].w, sv.w, acc[r][c]);
                }
            }
        }
    }
    // warp reduce over lanes (lanes partition j)
#pragma unroll
    for (int r = 0; r < RW; r++)
#pragma unroll
        for (int c = 0; c < C; c++) {
            float v = acc[r][c];
#pragma unroll
            for (int o = 16; o; o >>= 1) v += __shfl_xor_sync(0xffffffffu, v, o);
            if (lane == 0)
                Vpart[(size_t)blockIdx.y * (Nn * C) + (size_t)(i0 + r) * C + c] = v;
        }
}

// ---------------- 4) h1 = relu(dinv*(V1 + s1) + b1) ----------------
__global__ void epi1_kernel(const float* __restrict__ b1) {
    int i = blockIdx.x * 256 + threadIdx.x;
    float di = g_dinv[i];
#pragma unroll
    for (int c = 0; c < C1; c++) {
        float v = g_V1[0][i * C1 + c] + g_V1[1][i * C1 + c] +
                  g_V1[2][i * C1 + c] + g_V1[3][i * C1 + c];
        float o = di * (v + g_s1[i * C1 + c]) + b1[c];
        g_h1[i * C1 + c] = fmaxf(o, 0.f);
    }
}

// ---------------- 5) s2 = (h1 @ W2) * dinv ----------------
__global__ void u2_kernel(const float* __restrict__ W2) {
    __shared__ float w[C1 * C2];
    if (threadIdx.x < C1 * C2) w[threadIdx.x] = W2[threadIdx.x];
    __syncthreads();
    int i = blockIdx.x * 256 + threadIdx.x;
    float h[C1];
#pragma unroll
    for (int k = 0; k < C1; k++) h[k] = g_h1[i * C1 + k];
    float di = g_dinv[i];
#pragma unroll
    for (int c = 0; c < C2; c++) {
        float a = 0.f;
#pragma unroll
        for (int k = 0; k < C1; k++) a = fmaf(h[k], w[k * C2 + c], a);
        g_s2[i * C2 + c] = a * di;
    }
}

// ---------------- 6) per-block deterministic column sums of h2 (pre-b2) ----------------
__global__ void epi2_kernel() {
    __shared__ float red[256 * C2];
    int i = blockIdx.x * 256 + threadIdx.x;
    float di = g_dinv[i];
#pragma unroll
    for (int c = 0; c < C2; c++) {
        float v = g_V2[0][i * C2 + c] + g_V2[1][i * C2 + c] +
                  g_V2[2][i * C2 + c] + g_V2[3][i * C2 + c];
        red[threadIdx.x * C2 + c] = di * (v + g_s2[i * C2 + c]);
    }
    __syncthreads();
    for (int sft = 128; sft > 0; sft >>= 1) {
        if (threadIdx.x < sft) {
#pragma unroll
            for (int c = 0; c < C2; c++)
                red[threadIdx.x * C2 + c] += red[(threadIdx.x + sft) * C2 + c];
        }
        __syncthreads();
    }
    if (threadIdx.x < C2) g_part2[blockIdx.x][threadIdx.x] = red[threadIdx.x];
}

// ---------------- 7) head: z, z2, y ----------------
__global__ void final_kernel(const float* __restrict__ b2,
                             const float* __restrict__ fc1W, const float* __restrict__ fc1b,
                             const float* __restrict__ fcW, const float* __restrict__ fcb,
                             float* __restrict__ out) {
    if (threadIdx.x != 0 || blockIdx.x != 0) return;
    float z[C2];
    for (int c = 0; c < C2; c++) {
        float s = 0.f;
        for (int b = 0; b < Nn / 256; b++) s += g_part2[b][c];
        float m = s / (float)Nn + b2[c];
        z[c] = fmaxf(m, 0.f);
        out[c] = z[c];
    }
    float z2[5];
    for (int d = 0; d < 5; d++) {
        float a = fc1b[d];
        for (int c = 0; c < 5; c++) a += z[c] * fc1W[c * 5 + d];
        z2[d] = fmaxf(a, 0.f);
    }
    for (int e = 0; e < 2; e++) {
        float a = fcb[e];
        for (int d = 0; d < 5; d++) a += z2[d] * fcW[d * 2 + e];
        out[5 + e] = 1.f / (1.f + expf(-a));
    }
}

extern "C" void kernel_launch(void* const* d_in, const int* in_sizes, int n_in,
                              void* d_out, int out_size) {
    const float* x    = (const float*)d_in[0];
    const float* adj  = (const float*)d_in[1];
    const float* W1   = (const float*)d_in[2];
    const float* b1   = (const float*)d_in[3];
    const float* W2   = (const float*)d_in[4];
    const float* b2   = (const float*)d_in[5];
    const float* fc1W = (const float*)d_in[6];
    const float* fc1b = (const float*)d_in[7];
    const float* fcW  = (const float*)d_in[8];
    const float* fcb  = (const float*)d_in[9];
    float* out = (float*)d_out;

    deg_kernel<<<Nn, 256>>>(adj);
    u1_kernel<<<Nn / 8, 256>>>(x, W1);
    spmm_kernel<C1, true><<<dim3(Nn / RPB, JSPLIT), 256>>>(adj);
    epi1_kernel<<<Nn / 256, 256>>>(b1);
    u2_kernel<<<Nn / 256, 256>>>(W2);
    spmm_kernel<C2, false><<<dim3(Nn / RPB, JSPLIT), 256>>>(adj);
    epi2_kernel<<<Nn / 256, 256>>>();
    final_kernel<<<1, 32>>>(b2, fc1W, fc1b, fcW, fcb, out);
}

// round 11
// speedup vs baseline: 1.0022x; 1.0022x over previous
#include <cuda_runtime.h>
#include <math.h>

#define Nn 8192
#define FEAT 128
#define C1 10
#define C2 5
#define JSPLIT 4
#define TJ 512
#define RPB 32   // rows per block in spmm (8 warps x 4 rows)
#define RW 4     // rows per warp

// ---------------- scratch (static device globals; no allocation) ----------------
__device__ float g_dinv[Nn];
__device__ float g_s1[Nn * C1];
__device__ float g_h1[Nn * C1];
__device__ float g_s2[Nn * C2];
__device__ float g_V1[JSPLIT][Nn * C1];
__device__ float g_V2[JSPLIT][Nn * C2];
__device__ float g_part2[Nn / 256][C2];

// ---------------- 1) degree / dinv ----------------
__global__ void deg_kernel(const float* __restrict__ adj) {
    __shared__ int sc[256];
    int i = blockIdx.x;
    const float4* row = reinterpret_cast<const float4*>(adj + (size_t)i * Nn);
    int cnt = 0;
    for (int k = threadIdx.x; k < Nn / 4; k += 256) {
        float4 v = row[k];
        cnt += (v.x > 0.f) + (v.y > 0.f) + (v.z > 0.f) + (v.w > 0.f);
    }
    sc[threadIdx.x] = cnt;
    __syncthreads();
    for (int s = 128; s > 0; s >>= 1) {
        if (threadIdx.x < s) sc[threadIdx.x] += sc[threadIdx.x + s];
        __syncthreads();
    }
    if (threadIdx.x == 0) g_dinv[i] = rsqrtf((float)sc[0]);
}

// ---------------- 2) s1 = (x @ W1) * dinv ----------------
__global__ void u1_kernel(const float* __restrict__ x, const float* __restrict__ W1) {
    __shared__ float w[FEAT * C1];
    for (int t = threadIdx.x; t < FEAT * C1; t += 256) w[t] = W1[t];
    __syncthreads();
    int warp = threadIdx.x >> 5, lane = threadIdx.x & 31;
    int i = blockIdx.x * 8 + warp;
    float4 xv = reinterpret_cast<const float4*>(x + (size_t)i * FEAT)[lane];
    float xs[4] = {xv.x, xv.y, xv.z, xv.w};
    float acc[C1];
#pragma unroll
    for (int c = 0; c < C1; c++) acc[c] = 0.f;
#pragma unroll
    for (int kk = 0; kk < 4; kk++) {
        int k = lane * 4 + kk;
#pragma unroll
        for (int c = 0; c < C1; c++) acc[c] = fmaf(xs[kk], w[k * C1 + c], acc[c]);
    }
#pragma unroll
    for (int c = 0; c < C1; c++) {
        float v = acc[c];
#pragma unroll
        for (int o = 16; o; o >>= 1) v += __shfl_xor_sync(0xffffffffu, v, o);
        if (lane == 0) g_s1[i * C1 + c] = v * g_dinv[i];
    }
}

// ---------------- 3/5) SpMM: Vpart[split] = adj[:, jrange] @ s[jrange, :] ----------------
template <int C, bool L1>
__global__ void __launch_bounds__(256) spmm_kernel(const float* __restrict__ adj) {
    const float* __restrict__ s = L1 ? g_s1 : g_s2;
    float* __restrict__ Vpart = L1 ? &g_V1[0][0] : &g_V2[0][0];

    __shared__ float ss[C][TJ];
    int warp = threadIdx.x >> 5, lane = threadIdx.x & 31;
    int i0 = blockIdx.x * RPB + warp * RW;
    int jbase = blockIdx.y * (Nn / JSPLIT);

    float acc[RW][C];
#pragma unroll
    for (int r = 0; r < RW; r++)
#pragma unroll
        for (int c = 0; c < C; c++) acc[r][c] = 0.f;

    for (int jc = 0; jc < Nn / JSPLIT; jc += TJ) {
        __syncthreads();
        // coalesced global read of the s-tile, transposed store to smem [C][TJ]
        for (int t = threadIdx.x; t < TJ * C; t += 256) {
            float v = s[(size_t)(jbase + jc) * C + t];
            int c = t % C, jj = t / C;
            ss[c][jj] = v;
        }
        __syncthreads();
#pragma unroll
        for (int it = 0; it < TJ; it += 128) {
            int jj = it + lane * 4;
            const float* arow = adj + (size_t)i0 * Nn + (jbase + jc + jj);
            float4 a[RW];
#pragma unroll
            for (int r = 0; r < RW; r++)
                a[r] = *reinterpret_cast<const float4*>(arow + (size_t)r * Nn);
#pragma unroll
            for (int c = 0; c < C; c++) {
                float4 sv = *reinterpret_cast<const float4*>(&ss[c][jj]);
#pragma unroll
                for (int r = 0; r < RW; r++) {
                    acc[r][c] = fmaf(a[r].x, sv.x, acc[r][c]);
                    acc[r][c] = fmaf(a[r].y, sv.y, acc[r][c]);
                    acc[r][c] = fmaf(a[r].z, sv.z, acc[r][c]);
                    acc[r][c] = fmaf(a[r].w, sv.w, acc[r][c]);
                }
            }
        }
    }
    // warp reduce over lanes (lanes partition j)
#pragma unroll
    for (int r = 0; r < RW; r++)
#pragma unroll
        for (int c = 0; c < C; c++) {
            float v = acc[r][c];
#pragma unroll
            for (int o = 16; o; o >>= 1) v += __shfl_xor_sync(0xffffffffu, v, o);
            if (lane == 0)
                Vpart[(size_t)blockIdx.y * (Nn * C) + (size_t)(i0 + r) * C + c] = v;
        }
}

// ---------------- 4) h1 = relu(dinv*(V1 + s1) + b1) ----------------
__global__ void epi1_kernel(const float* __restrict__ b1) {
    int i = blockIdx.x * 256 + threadIdx.x;
    float di = g_dinv[i];
#pragma unroll
    for (int c = 0; c < C1; c++) {
        float v = g_V1[0][i * C1 + c] + g_V1[1][i * C1 + c] +
                  g_V1[2][i * C1 + c] + g_V1[3][i * C1 + c];
        float o = di * (v + g_s1[i * C1 + c]) + b1[c];
        g_h1[i * C1 + c] = fmaxf(o, 0.f);
    }
}

// ---------------- 5) s2 = (h1 @ W2) * dinv ----------------
__global__ void u2_kernel(const float* __restrict__ W2) {
    __shared__ float w[C1 * C2];
    if (threadIdx.x < C1 * C2) w[threadIdx.x] = W2[threadIdx.x];
    __syncthreads();
    int i = blockIdx.x * 256 + threadIdx.x;
    float h[C1];
#pragma unroll
    for (int k = 0; k < C1; k++) h[k] = g_h1[i * C1 + k];
    float di = g_dinv[i];
#pragma unroll
    for (int c = 0; c < C2; c++) {
        float a = 0.f;
#pragma unroll
        for (int k = 0; k < C1; k++) a = fmaf(h[k], w[k * C2 + c], a);
        g_s2[i * C2 + c] = a * di;
    }
}

// ---------------- 6) per-block deterministic column sums of h2 (pre-b2) ----------------
__global__ void epi2_kernel() {
    __shared__ float red[256 * C2];
    int i = blockIdx.x * 256 + threadIdx.x;
    float di = g_dinv[i];
#pragma unroll
    for (int c = 0; c < C2; c++) {
        float v = g_V2[0][i * C2 + c] + g_V2[1][i * C2 + c] +
                  g_V2[2][i * C2 + c] + g_V2[3][i * C2 + c];
        red[threadIdx.x * C2 + c] = di * (v + g_s2[i * C2 + c]);
    }
    __syncthreads();
    for (int sft = 128; sft > 0; sft >>= 1) {
        if (threadIdx.x < sft) {
#pragma unroll
            for (int c = 0; c < C2; c++)
                red[threadIdx.x * C2 + c] += red[(threadIdx.x + sft) * C2 + c];
        }
        __syncthreads();
    }
    if (threadIdx.x < C2) g_part2[blockIdx.x][threadIdx.x] = red[threadIdx.x];
}

// ---------------- 7) head: z, z2, y ----------------
__global__ void final_kernel(const float* __restrict__ b2,
                             const float* __restrict__ fc1W, const float* __restrict__ fc1b,
                             const float* __restrict__ fcW, const float* __restrict__ fcb,
                             float* __restrict__ out) {
    if (threadIdx.x != 0 || blockIdx.x != 0) return;
    float z[C2];
    for (int c = 0; c < C2; c++) {
        float s = 0.f;
        for (int b = 0; b < Nn / 256; b++) s += g_part2[b][c];
        float m = s / (float)Nn + b2[c];
        z[c] = fmaxf(m, 0.f);
        out[c] = z[c];
    }
    float z2[5];
    for (int d = 0; d < 5; d++) {
        float a = fc1b[d];
        for (int c = 0; c < 5; c++) a += z[c] * fc1W[c * 5 + d];
        z2[d] = fmaxf(a, 0.f);
    }
    for (int e = 0; e < 2; e++) {
        float a = fcb[e];
        for (int d = 0; d < 5; d++) a += z2[d] * fcW[d * 2 + e];
        out[5 + e] = 1.f / (1.f + expf(-a));
    }
}

extern "C" void kernel_launch(void* const* d_in, const int* in_sizes, int n_in,
                              void* d_out, int out_size) {
    const float* x    = (const float*)d_in[0];
    const float* adj  = (const float*)d_in[1];
    const float* W1   = (const float*)d_in[2];
    const float* b1   = (const float*)d_in[3];
    const float* W2   = (const float*)d_in[4];
    const float* b2   = (const float*)d_in[5];
    const float* fc1W = (const float*)d_in[6];
    const float* fc1b = (const float*)d_in[7];
    const float* fcW  = (const float*)d_in[8];
    const float* fcb  = (const float*)d_in[9];
    float* out = (float*)d_out;

    deg_kernel<<<Nn, 256>>>(adj);
    u1_kernel<<<Nn / 8, 256>>>(x, W1);
    spmm_kernel<C1, true><<<dim3(Nn / RPB, JSPLIT), 256>>>(adj);
    epi1_kernel<<<Nn / 256, 256>>>(b1);
    u2_kernel<<<Nn / 256, 256>>>(W2);
    spmm_kernel<C2, false><<<dim3(Nn / RPB, JSPLIT), 256>>>(adj);
    epi2_kernel<<<Nn / 256, 256>>>();
    final_kernel<<<1, 32>>>(b2, fc1W, fc1b, fcW, fcb, out);
}